// round 6
// baseline (speedup 1.0000x reference)
#include <cuda_runtime.h>
#include <cuda_fp16.h>
#include <cstdint>

#define NPTS   2000000
#define NTILES 7813          // ceil(2,000,000 / 256); last tile clamps

// dynamic shared layout (bytes)
#define XS_OFF 0             // half [256][120]  (stride 240B, LDSM conflict-free)
#define W1_OFF 61440         // half [64][120]   W1S[j][k] = W1[k][j], k pad 105->112 zeros
#define W2_OFF 76800         // half [64][72]    W2S[j][k] = W2[k][j]
#define W3_OFF 86016         // float4 [64]
#define B1_OFF 87040         // float [64]
#define B2_OFF 87296         // float [64]
#define B3_OFF 87552         // float [4]
#define SMEM_BYTES 87568

__device__ __forceinline__ uint32_t pk(float a, float b) {
    __half2 h = __floats2half2_rn(a, b);
    return *reinterpret_cast<uint32_t*>(&h);
}

__device__ __forceinline__ float2 upk(uint32_t v) {
    __half2 h = *reinterpret_cast<__half2*>(&v);
    return __half22float2(h);
}

__device__ __forceinline__ void sts8(__half* p,
    float a, float b, float c, float d, float e, float f, float g, float h) {
    uint4 u;
    u.x = pk(a, b); u.y = pk(c, d); u.z = pk(e, f); u.w = pk(g, h);
    *reinterpret_cast<uint4*>(p) = u;
}

// D = A(16x16,f16,row) * B(16x8,f16,col) + D, fp16 accumulate
__device__ __forceinline__ void mma16816h(uint32_t* c,
    const uint32_t* a, uint32_t b0, uint32_t b1) {
    asm volatile(
        "mma.sync.aligned.m16n8k16.row.col.f16.f16.f16.f16 "
        "{%0,%1}, {%2,%3,%4,%5}, {%6,%7}, {%0,%1};\n"
        : "+r"(c[0]), "+r"(c[1])
        : "r"(a[0]), "r"(a[1]), "r"(a[2]), "r"(a[3]), "r"(b0), "r"(b1));
}

__device__ __forceinline__ void ldsm4(uint32_t* r, uint32_t addr) {
    asm volatile(
        "ldmatrix.sync.aligned.m8n8.x4.shared.b16 {%0,%1,%2,%3}, [%4];\n"
        : "=r"(r[0]), "=r"(r[1]), "=r"(r[2]), "=r"(r[3]) : "r"(addr));
}

__global__ void __launch_bounds__(128, 2)
fused_encode_mlp(const float* __restrict__ bases,
                 const float* __restrict__ normals,
                 const float* __restrict__ enc,
                 const float* __restrict__ W1, const float* __restrict__ b1,
                 const float* __restrict__ W2, const float* __restrict__ b2,
                 const float* __restrict__ W3, const float* __restrict__ b3,
                 float* __restrict__ out)
{
    extern __shared__ char smem[];
    __half*  XS  = reinterpret_cast<__half*>(smem + XS_OFF);
    __half*  W1S = reinterpret_cast<__half*>(smem + W1_OFF);
    __half*  W2S = reinterpret_cast<__half*>(smem + W2_OFF);
    float4*  W3S = reinterpret_cast<float4*>(smem + W3_OFF);
    float*   B1S = reinterpret_cast<float*>(smem + B1_OFF);
    float*   B2S = reinterpret_cast<float*>(smem + B2_OFF);
    float*   B3S = reinterpret_cast<float*>(smem + B3_OFF);

    const int tid  = threadIdx.x;
    const int lane = tid & 31;
    const int wp   = tid >> 5;
    const int g    = lane >> 2;
    const int tig  = lane & 3;
    const int warpRow = wp * 64;     // each warp owns M=64 rows of the 256-row tile

    // ---- stage weights once per CTA ----
    for (int i = tid; i < 64 * 120; i += 128) W1S[i] = __float2half(0.f);
    __syncthreads();
    for (int i = tid; i < 105 * 64; i += 128) {
        int k = i >> 6, j = i & 63;
        W1S[j * 120 + k] = __float2half(W1[i]);
    }
    for (int i = tid; i < 64 * 64; i += 128) {
        int k = i >> 6, j = i & 63;
        W2S[j * 72 + k] = __float2half(W2[i]);
    }
    if (tid < 64) {
        W3S[tid] = make_float4(W3[tid * 3 + 0], W3[tid * 3 + 1], W3[tid * 3 + 2], 0.f);
        B1S[tid] = b1[tid];
        B2S[tid] = b2[tid];
    }
    if (tid < 3) B3S[tid] = b3[tid];
    __syncthreads();

    // ---- ldmatrix addresses ----
    const uint32_t xs_b = (uint32_t)__cvta_generic_to_shared(XS);
    const uint32_t w1_b = (uint32_t)__cvta_generic_to_shared(W1S);
    const uint32_t w2_b = (uint32_t)__cvta_generic_to_shared(W2S);

    const int aRowIn = (lane & 7) + ((lane >> 3) & 1) * 8;
    const int aCol   = ((lane >> 4) & 1) * 16;
    uint32_t baseA[4];
    #pragma unroll
    for (int m = 0; m < 4; m++)
        baseA[m] = xs_b + (uint32_t)((warpRow + m * 16 + aRowIn) * 240 + aCol);

    const int bRowIn = (lane & 7) + ((lane >> 4) & 1) * 8;
    const int bCol   = ((lane >> 3) & 1) * 16;
    uint32_t baseB1[4];
    #pragma unroll
    for (int p = 0; p < 4; p++)
        baseB1[p] = w1_b + (uint32_t)((p * 16 + bRowIn) * 240 + bCol);

    // ---- hoist layer-2 B fragments into registers (tile-invariant, 64 regs) ----
    uint32_t B2f[4][4][4];
    #pragma unroll
    for (int kk = 0; kk < 4; kk++)
        #pragma unroll
        for (int p = 0; p < 4; p++) {
            uint32_t addr = w2_b + (uint32_t)((p * 16 + bRowIn) * 144 + bCol) + kk * 32;
            ldsm4(B2f[kk][p], addr);
        }

    const float b3x = B3S[0], b3y = B3S[1], b3z = B3S[2];

    for (int tile = blockIdx.x; tile < NTILES; tile += gridDim.x) {
        // ================= features: 2 points per thread -> SMEM =================
        #pragma unroll
        for (int q = 0; q < 2; q++) {
            int prow = tile * 256 + q * 128 + tid;
            int row  = prow < NPTS ? prow : NPTS - 1;        // clamp (identical dup work)
            __half* xr = XS + (q * 128 + tid) * 120;

            const float4* ep = reinterpret_cast<const float4*>(enc + (size_t)row * 20);
            float4 e0 = ep[0], e1 = ep[1], e2 = ep[2], e3 = ep[3], e4v = ep[4];
            sts8(xr + 0, e0.x, e0.y, e0.z, e0.w, e1.x, e1.y, e1.z, e1.w);
            sts8(xr + 8, e2.x, e2.y, e2.z, e2.w, e3.x, e3.y, e3.z, e3.w);

            float bx = bases[row * 3 + 0], by = bases[row * 3 + 1], bz = bases[row * 3 + 2];

            float sn[8][3], cs[8][3];
            __sincosf(2.f * bx, &sn[0][0], &cs[0][0]);
            __sincosf(2.f * by, &sn[0][1], &cs[0][1]);
            __sincosf(2.f * bz, &sn[0][2], &cs[0][2]);
            #pragma unroll
            for (int i = 1; i < 8; i++) {
                #pragma unroll
                for (int d = 0; d < 3; d++) {
                    float s = sn[i - 1][d], c = cs[i - 1][d];
                    sn[i][d] = 2.f * s * c;
                    cs[i][d] = 1.f - 2.f * s * s;
                }
            }
            sts8(xr + 16, e4v.x, e4v.y, e4v.z, e4v.w, bx, by, bz, sn[0][0]);
            sts8(xr + 24, sn[0][1], sn[0][2], cs[0][0], cs[0][1], cs[0][2], sn[1][0], sn[1][1], sn[1][2]);
            sts8(xr + 32, cs[1][0], cs[1][1], cs[1][2], sn[2][0], sn[2][1], sn[2][2], cs[2][0], cs[2][1]);
            sts8(xr + 40, cs[2][2], sn[3][0], sn[3][1], sn[3][2], cs[3][0], cs[3][1], cs[3][2], sn[4][0]);
            sts8(xr + 48, sn[4][1], sn[4][2], cs[4][0], cs[4][1], cs[4][2], sn[5][0], sn[5][1], sn[5][2]);
            sts8(xr + 56, cs[5][0], cs[5][1], cs[5][2], sn[6][0], sn[6][1], sn[6][2], cs[6][0], cs[6][1]);

            float n0 = normals[row * 2 + 0], n1 = normals[row * 2 + 1];
            sts8(xr + 64, cs[6][2], sn[7][0], sn[7][1], sn[7][2], cs[7][0], cs[7][1], cs[7][2], n0);

            float bl0[16], bl1[16];
            {
                const float V1 = 0.80073740291680f;   // exp(-50/225)
                const float V2 = 0.64118038843357f;   // exp(-100/225)
                float E0 = __expf(-50.f * n0 * n0);
                float r0 = __expf(6.66666667f * n0) * V1;
                float E1 = __expf(-50.f * n1 * n1);
                float r1 = __expf(6.66666667f * n1) * V1;
                bl0[0] = E0; bl1[0] = E1;
                #pragma unroll
                for (int k = 1; k < 16; k++) {
                    E0 *= r0; r0 *= V2; bl0[k] = E0;
                    E1 *= r1; r1 *= V2; bl1[k] = E1;
                }
            }
            sts8(xr + 72,  n1, bl0[0], bl0[1], bl0[2], bl0[3], bl0[4], bl0[5], bl0[6]);
            sts8(xr + 80,  bl0[7], bl0[8], bl0[9], bl0[10], bl0[11], bl0[12], bl0[13], bl0[14]);
            sts8(xr + 88,  bl0[15], bl1[0], bl1[1], bl1[2], bl1[3], bl1[4], bl1[5], bl1[6]);
            sts8(xr + 96,  bl1[7], bl1[8], bl1[9], bl1[10], bl1[11], bl1[12], bl1[13], bl1[14]);
            sts8(xr + 104, bl1[15], 0.f, 0.f, 0.f, 0.f, 0.f, 0.f, 0.f);
        }

        __syncthreads();   // warps read rows written by other warps

        // ================= layer 1: [64 x 112] @ [112 x 64], f16 acc =================
        uint32_t acc[4][8][2];
        #pragma unroll
        for (int m = 0; m < 4; m++)
            #pragma unroll
            for (int nt = 0; nt < 8; nt++) { acc[m][nt][0] = 0u; acc[m][nt][1] = 0u; }

        #pragma unroll
        for (int kk = 0; kk < 7; kk++) {
            uint32_t A[4][4];
            #pragma unroll
            for (int m = 0; m < 4; m++) ldsm4(A[m], baseA[m] + kk * 32);
            #pragma unroll
            for (int p = 0; p < 4; p++) {
                uint32_t b[4];
                ldsm4(b, baseB1[p] + kk * 32);
                #pragma unroll
                for (int m = 0; m < 4; m++) {
                    mma16816h(acc[m][2 * p],     A[m], b[0], b[1]);
                    mma16816h(acc[m][2 * p + 1], A[m], b[2], b[3]);
                }
            }
        }

        // bias + sin, repack in place (f16 C-frag layout == f16 A-frag layout)
        #pragma unroll
        for (int m = 0; m < 4; m++)
            #pragma unroll
            for (int nt = 0; nt < 8; nt++) {
                float bv0 = B1S[nt * 8 + tig * 2];
                float bv1 = B1S[nt * 8 + tig * 2 + 1];
                float2 zlo = upk(acc[m][nt][0]);
                float2 zhi = upk(acc[m][nt][1]);
                acc[m][nt][0] = pk(__sinf(zlo.x + bv0), __sinf(zlo.y + bv1));
                acc[m][nt][1] = pk(__sinf(zhi.x + bv0), __sinf(zhi.y + bv1));
            }

        // ================= layer 2: [64 x 64] @ [64 x 64], B from registers =================
        uint32_t ac2[4][8][2];
        #pragma unroll
        for (int m = 0; m < 4; m++)
            #pragma unroll
            for (int nt = 0; nt < 8; nt++) { ac2[m][nt][0] = 0u; ac2[m][nt][1] = 0u; }

        #pragma unroll
        for (int kk = 0; kk < 4; kk++)
            #pragma unroll
            for (int p = 0; p < 4; p++)
                #pragma unroll
                for (int m = 0; m < 4; m++) {
                    uint32_t a[4] = { acc[m][2 * kk][0], acc[m][2 * kk][1],
                                      acc[m][2 * kk + 1][0], acc[m][2 * kk + 1][1] };
                    mma16816h(ac2[m][2 * p],     a, B2f[kk][p][0], B2f[kk][p][1]);
                    mma16816h(ac2[m][2 * p + 1], a, B2f[kk][p][2], B2f[kk][p][3]);
                }

        // ================= bias + sin + layer 3 + residual =================
        #pragma unroll
        for (int m = 0; m < 4; m++) {
            float pA0 = 0.f, pA1 = 0.f, pA2 = 0.f;   // row g
            float pB0 = 0.f, pB1 = 0.f, pB2 = 0.f;   // row g+8
            #pragma unroll
            for (int nt = 0; nt < 8; nt++) {
                float bv0 = B2S[nt * 8 + tig * 2];
                float bv1 = B2S[nt * 8 + tig * 2 + 1];
                float2 zlo = upk(ac2[m][nt][0]);
                float2 zhi = upk(ac2[m][nt][1]);
                float a0 = __sinf(zlo.x + bv0), a1 = __sinf(zlo.y + bv1);
                float a2 = __sinf(zhi.x + bv0), a3 = __sinf(zhi.y + bv1);
                float4 w0 = W3S[nt * 8 + tig * 2];
                float4 w1 = W3S[nt * 8 + tig * 2 + 1];
                pA0 += a0 * w0.x + a1 * w1.x;
                pA1 += a0 * w0.y + a1 * w1.y;
                pA2 += a0 * w0.z + a1 * w1.z;
                pB0 += a2 * w0.x + a3 * w1.x;
                pB1 += a2 * w0.y + a3 * w1.y;
                pB2 += a2 * w0.z + a3 * w1.z;
            }
            pA0 += __shfl_xor_sync(0xffffffffu, pA0, 1); pA0 += __shfl_xor_sync(0xffffffffu, pA0, 2);
            pA1 += __shfl_xor_sync(0xffffffffu, pA1, 1); pA1 += __shfl_xor_sync(0xffffffffu, pA1, 2);
            pA2 += __shfl_xor_sync(0xffffffffu, pA2, 1); pA2 += __shfl_xor_sync(0xffffffffu, pA2, 2);
            pB0 += __shfl_xor_sync(0xffffffffu, pB0, 1); pB0 += __shfl_xor_sync(0xffffffffu, pB0, 2);
            pB1 += __shfl_xor_sync(0xffffffffu, pB1, 1); pB1 += __shfl_xor_sync(0xffffffffu, pB1, 2);
            pB2 += __shfl_xor_sync(0xffffffffu, pB2, 1); pB2 += __shfl_xor_sync(0xffffffffu, pB2, 2);

            if (tig == 0) {
                int rA = tile * 256 + warpRow + m * 16 + g;
                int wA = rA < NPTS ? rA : NPTS - 1;          // clamped dup writes identical
                out[wA * 3 + 0] = bases[wA * 3 + 0] + pA0 + b3x;
                out[wA * 3 + 1] = bases[wA * 3 + 1] + pA1 + b3y;
                out[wA * 3 + 2] = bases[wA * 3 + 2] + pA2 + b3z;
                int rB = rA + 8;
                int wB = rB < NPTS ? rB : NPTS - 1;
                out[wB * 3 + 0] = bases[wB * 3 + 0] + pB0 + b3x;
                out[wB * 3 + 1] = bases[wB * 3 + 1] + pB1 + b3y;
                out[wB * 3 + 2] = bases[wB * 3 + 2] + pB2 + b3z;
            }
        }
        __syncthreads();   // all reads of XS done before next tile overwrites
    }
}

extern "C" void kernel_launch(void* const* d_in, const int* in_sizes, int n_in,
                              void* d_out, int out_size) {
    const float* bases   = (const float*)d_in[0];
    const float* normals = (const float*)d_in[1];
    const float* enc     = (const float*)d_in[2];
    const float* W1      = (const float*)d_in[3];
    const float* b1      = (const float*)d_in[4];
    const float* W2      = (const float*)d_in[5];
    const float* b2      = (const float*)d_in[6];
    const float* W3      = (const float*)d_in[7];
    const float* b3      = (const float*)d_in[8];
    float* out = (float*)d_out;

    cudaFuncSetAttribute(fused_encode_mlp,
                         cudaFuncAttributeMaxDynamicSharedMemorySize, SMEM_BYTES);

    // 2 CTAs/SM x 148 SMs; 256-reg/thread budget enables B2-in-registers
    fused_encode_mlp<<<296, 128, SMEM_BYTES>>>(bases, normals, enc,
                                               W1, b1, W2, b2, W3, b3, out);
}

// round 7
// speedup vs baseline: 1.3564x; 1.3564x over previous
#include <cuda_runtime.h>
#include <cuda_fp16.h>
#include <cstdint>

#define NPTS  2000000
#define TILES 15625          // 2,000,000 / 128 exactly

// dynamic shared layout (bytes)
#define XS_OFF 0             // half [128][120]  (stride 240B, LDSM conflict-free)
#define W1_OFF 30720         // half [64][120]   W1S[j][k] = W1[k][j], k pad 105->112 zeros
#define W2_OFF 46080         // half [64][72]    W2S[j][k] = W2[k][j]
#define W3_OFF 55296         // half [8][72]     W3hS[n][k] = W3[k*3+n] (n<3), else 0
#define SMEM_BYTES 56448

__device__ __forceinline__ uint32_t pk(float a, float b) {
    __half2 h = __floats2half2_rn(a, b);
    return *reinterpret_cast<uint32_t*>(&h);
}

__device__ __forceinline__ float2 upk(uint32_t v) {
    __half2 h = *reinterpret_cast<__half2*>(&v);
    return __half22float2(h);
}

__device__ __forceinline__ void sts8(__half* p,
    float a, float b, float c, float d, float e, float f, float g, float h) {
    uint4 u;
    u.x = pk(a, b); u.y = pk(c, d); u.z = pk(e, f); u.w = pk(g, h);
    *reinterpret_cast<uint4*>(p) = u;
}

// f16 accumulate
__device__ __forceinline__ void mma16816h(uint32_t* c,
    const uint32_t* a, uint32_t b0, uint32_t b1) {
    asm volatile(
        "mma.sync.aligned.m16n8k16.row.col.f16.f16.f16.f16 "
        "{%0,%1}, {%2,%3,%4,%5}, {%6,%7}, {%0,%1};\n"
        : "+r"(c[0]), "+r"(c[1])
        : "r"(a[0]), "r"(a[1]), "r"(a[2]), "r"(a[3]), "r"(b0), "r"(b1));
}

// f32 accumulate (layer 3)
__device__ __forceinline__ void mma16816f(float* c,
    const uint32_t* a, uint32_t b0, uint32_t b1) {
    asm volatile(
        "mma.sync.aligned.m16n8k16.row.col.f32.f16.f16.f32 "
        "{%0,%1,%2,%3}, {%4,%5,%6,%7}, {%8,%9}, {%0,%1,%2,%3};\n"
        : "+f"(c[0]), "+f"(c[1]), "+f"(c[2]), "+f"(c[3])
        : "r"(a[0]), "r"(a[1]), "r"(a[2]), "r"(a[3]), "r"(b0), "r"(b1));
}

__device__ __forceinline__ void ldsm4(uint32_t* r, uint32_t addr) {
    asm volatile(
        "ldmatrix.sync.aligned.m8n8.x4.shared.b16 {%0,%1,%2,%3}, [%4];\n"
        : "=r"(r[0]), "=r"(r[1]), "=r"(r[2]), "=r"(r[3]) : "r"(addr));
}

__global__ void __launch_bounds__(128, 4)
fused_encode_mlp(const float* __restrict__ bases,
                 const float* __restrict__ normals,
                 const float* __restrict__ enc,
                 const float* __restrict__ W1, const float* __restrict__ b1,
                 const float* __restrict__ W2, const float* __restrict__ b2,
                 const float* __restrict__ W3, const float* __restrict__ b3,
                 float* __restrict__ out)
{
    extern __shared__ char smem[];
    __half* XS   = reinterpret_cast<__half*>(smem + XS_OFF);
    __half* W1S  = reinterpret_cast<__half*>(smem + W1_OFF);
    __half* W2S  = reinterpret_cast<__half*>(smem + W2_OFF);
    __half* W3hS = reinterpret_cast<__half*>(smem + W3_OFF);

    const int tid  = threadIdx.x;
    const int lane = tid & 31;
    const int wp   = tid >> 5;
    const int g    = lane >> 2;
    const int tig  = lane & 3;
    const int warpRow = wp * 32;

    // ---- stage weights once per CTA ----
    for (int i = tid; i < 64 * 120; i += 128) W1S[i] = __float2half(0.f);
    for (int i = tid; i < 8 * 72; i += 128)   W3hS[i] = __float2half(0.f);
    __syncthreads();
    for (int i = tid; i < 105 * 64; i += 128) {
        int k = i >> 6, j = i & 63;
        W1S[j * 120 + k] = __float2half(W1[i]);
    }
    for (int i = tid; i < 64 * 64; i += 128) {
        int k = i >> 6, j = i & 63;
        W2S[j * 72 + k] = __float2half(W2[i]);
    }
    if (tid < 64) {   // W3hS[n][k] = W3[k][n] for n<3 (rows 3..7 stay zero)
        int k = tid;
        W3hS[0 * 72 + k] = __float2half(W3[k * 3 + 0]);
        W3hS[1 * 72 + k] = __float2half(W3[k * 3 + 1]);
        W3hS[2 * 72 + k] = __float2half(W3[k * 3 + 2]);
    }
    __syncthreads();

    // ---- ldmatrix addresses ----
    const uint32_t xs_b  = (uint32_t)__cvta_generic_to_shared(XS);
    const uint32_t w1_b  = (uint32_t)__cvta_generic_to_shared(W1S);
    const uint32_t w2_b  = (uint32_t)__cvta_generic_to_shared(W2S);
    const uint32_t w3_b  = (uint32_t)__cvta_generic_to_shared(W3hS);

    const int aRowIn = (lane & 7) + ((lane >> 3) & 1) * 8;
    const int aCol   = ((lane >> 4) & 1) * 16;
    uint32_t baseA0 = xs_b + (uint32_t)((warpRow + aRowIn) * 240 + aCol);
    uint32_t baseA1 = baseA0 + 16u * 240u;

    const int bRowIn = (lane & 7) + ((lane >> 4) & 1) * 8;
    const int bCol   = ((lane >> 3) & 1) * 16;
    uint32_t baseB1[4], baseB2[4];
    #pragma unroll
    for (int p = 0; p < 4; p++) {
        baseB1[p] = w1_b + (uint32_t)((p * 16 + bRowIn) * 240 + bCol);
        baseB2[p] = w2_b + (uint32_t)((p * 16 + bRowIn) * 144 + bCol);
    }

    // ---- hoist W3 B-fragments (N=8 tile; lanes 8-15 read dup rows, frags 2,3 unused) ----
    uint32_t B3f[4][2];
    {
        uint32_t baseB3 = w3_b + (uint32_t)((lane & 7) * 144 + bCol);
        #pragma unroll
        for (int kk = 0; kk < 4; kk++) {
            uint32_t t[4];
            ldsm4(t, baseB3 + kk * 32);
            B3f[kk][0] = t[0]; B3f[kk][1] = t[1];
        }
    }

    // ---- tile-invariant bias-init registers ----
    uint32_t biasL1[8], biasL2[8];
    #pragma unroll
    for (int nt = 0; nt < 8; nt++) {
        biasL1[nt] = pk(b1[nt * 8 + tig * 2], b1[nt * 8 + tig * 2 + 1]);
        biasL2[nt] = pk(b2[nt * 8 + tig * 2], b2[nt * 8 + tig * 2 + 1]);
    }
    const float i3a = (tig == 0) ? b3[0] : (tig == 1) ? b3[2] : 0.f;   // C col 2*tig
    const float i3b = (tig == 0) ? b3[1] : 0.f;                        // C col 2*tig+1

    for (int tile = blockIdx.x; tile < TILES; tile += gridDim.x) {
        const int row = tile * 128 + tid;

        // ================= features -> SMEM (fp16, cols 0..111) =================
        __half* xr = XS + tid * 120;

        const float4* ep = reinterpret_cast<const float4*>(enc + (size_t)row * 20);
        float4 e0 = ep[0], e1 = ep[1], e2 = ep[2], e3 = ep[3], e4v = ep[4];
        sts8(xr + 0, e0.x, e0.y, e0.z, e0.w, e1.x, e1.y, e1.z, e1.w);
        sts8(xr + 8, e2.x, e2.y, e2.z, e2.w, e3.x, e3.y, e3.z, e3.w);

        float bx = bases[row * 3 + 0], by = bases[row * 3 + 1], bz = bases[row * 3 + 2];

        float sn[8][3], cs[8][3];
        __sincosf(2.f * bx, &sn[0][0], &cs[0][0]);
        __sincosf(2.f * by, &sn[0][1], &cs[0][1]);
        __sincosf(2.f * bz, &sn[0][2], &cs[0][2]);
        #pragma unroll
        for (int i = 1; i < 8; i++) {
            #pragma unroll
            for (int d = 0; d < 3; d++) {
                float s = sn[i - 1][d], c = cs[i - 1][d];
                sn[i][d] = 2.f * s * c;
                cs[i][d] = 1.f - 2.f * s * s;
            }
        }
        sts8(xr + 16, e4v.x, e4v.y, e4v.z, e4v.w, bx, by, bz, sn[0][0]);
        sts8(xr + 24, sn[0][1], sn[0][2], cs[0][0], cs[0][1], cs[0][2], sn[1][0], sn[1][1], sn[1][2]);
        sts8(xr + 32, cs[1][0], cs[1][1], cs[1][2], sn[2][0], sn[2][1], sn[2][2], cs[2][0], cs[2][1]);
        sts8(xr + 40, cs[2][2], sn[3][0], sn[3][1], sn[3][2], cs[3][0], cs[3][1], cs[3][2], sn[4][0]);
        sts8(xr + 48, sn[4][1], sn[4][2], cs[4][0], cs[4][1], cs[4][2], sn[5][0], sn[5][1], sn[5][2]);
        sts8(xr + 56, cs[5][0], cs[5][1], cs[5][2], sn[6][0], sn[6][1], sn[6][2], cs[6][0], cs[6][1]);

        float n0 = normals[row * 2 + 0], n1 = normals[row * 2 + 1];
        sts8(xr + 64, cs[6][2], sn[7][0], sn[7][1], sn[7][2], cs[7][0], cs[7][1], cs[7][2], n0);

        float bl0[16], bl1[16];
        {
            const float V1 = 0.80073740291680f;   // exp(-50/225)
            const float V2 = 0.64118038843357f;   // exp(-100/225)
            float E0 = __expf(-50.f * n0 * n0);
            float r0 = __expf(6.66666667f * n0) * V1;
            float E1 = __expf(-50.f * n1 * n1);
            float r1 = __expf(6.66666667f * n1) * V1;
            bl0[0] = E0; bl1[0] = E1;
            #pragma unroll
            for (int k = 1; k < 16; k++) {
                E0 *= r0; r0 *= V2; bl0[k] = E0;
                E1 *= r1; r1 *= V2; bl1[k] = E1;
            }
        }
        sts8(xr + 72,  n1, bl0[0], bl0[1], bl0[2], bl0[3], bl0[4], bl0[5], bl0[6]);
        sts8(xr + 80,  bl0[7], bl0[8], bl0[9], bl0[10], bl0[11], bl0[12], bl0[13], bl0[14]);
        sts8(xr + 88,  bl0[15], bl1[0], bl1[1], bl1[2], bl1[3], bl1[4], bl1[5], bl1[6]);
        sts8(xr + 96,  bl1[7], bl1[8], bl1[9], bl1[10], bl1[11], bl1[12], bl1[13], bl1[14]);
        sts8(xr + 104, bl1[15], 0.f, 0.f, 0.f, 0.f, 0.f, 0.f, 0.f);

        __syncwarp();   // warp reads only its own 32 rows

        // ================= layer 1: bias-initialized f16 accumulators =================
        uint32_t acc[2][8][2];
        #pragma unroll
        for (int mt = 0; mt < 2; mt++)
            #pragma unroll
            for (int nt = 0; nt < 8; nt++) {
                acc[mt][nt][0] = biasL1[nt];
                acc[mt][nt][1] = biasL1[nt];
            }

        #pragma unroll
        for (int kk = 0; kk < 7; kk++) {
            uint32_t aA[4], aB[4];
            ldsm4(aA, baseA0 + kk * 32);
            ldsm4(aB, baseA1 + kk * 32);
            #pragma unroll
            for (int p = 0; p < 4; p++) {
                uint32_t b[4];
                ldsm4(b, baseB1[p] + kk * 32);
                mma16816h(acc[0][2 * p],     aA, b[0], b[1]);
                mma16816h(acc[0][2 * p + 1], aA, b[2], b[3]);
                mma16816h(acc[1][2 * p],     aB, b[0], b[1]);
                mma16816h(acc[1][2 * p + 1], aB, b[2], b[3]);
            }
        }

        // sin + repack in place (bias already inside)
        #pragma unroll
        for (int mt = 0; mt < 2; mt++)
            #pragma unroll
            for (int nt = 0; nt < 8; nt++) {
                float2 zlo = upk(acc[mt][nt][0]);
                float2 zhi = upk(acc[mt][nt][1]);
                acc[mt][nt][0] = pk(__sinf(zlo.x), __sinf(zlo.y));
                acc[mt][nt][1] = pk(__sinf(zhi.x), __sinf(zhi.y));
            }

        // ================= layer 2: bias-initialized f16 accumulators =================
        uint32_t ac2[2][8][2];
        #pragma unroll
        for (int mt = 0; mt < 2; mt++)
            #pragma unroll
            for (int nt = 0; nt < 8; nt++) {
                ac2[mt][nt][0] = biasL2[nt];
                ac2[mt][nt][1] = biasL2[nt];
            }

        #pragma unroll
        for (int kk = 0; kk < 4; kk++) {
            #pragma unroll
            for (int p = 0; p < 4; p++) {
                uint32_t b[4];
                ldsm4(b, baseB2[p] + kk * 32);
                #pragma unroll
                for (int mt = 0; mt < 2; mt++) {
                    uint32_t a[4] = { acc[mt][2 * kk][0], acc[mt][2 * kk][1],
                                      acc[mt][2 * kk + 1][0], acc[mt][2 * kk + 1][1] };
                    mma16816h(ac2[mt][2 * p],     a, b[0], b[1]);
                    mma16816h(ac2[mt][2 * p + 1], a, b[2], b[3]);
                }
            }
        }

        // sin + repack act2 in place -> A-fragments for layer 3
        #pragma unroll
        for (int mt = 0; mt < 2; mt++)
            #pragma unroll
            for (int nt = 0; nt < 8; nt++) {
                float2 zlo = upk(ac2[mt][nt][0]);
                float2 zhi = upk(ac2[mt][nt][1]);
                ac2[mt][nt][0] = pk(__sinf(zlo.x), __sinf(zlo.y));
                ac2[mt][nt][1] = pk(__sinf(zhi.x), __sinf(zhi.y));
            }

        // ================= layer 3 via MMA (N=8 pad, f32 acc, b3 in init) =================
        #pragma unroll
        for (int mt = 0; mt < 2; mt++) {
            float c[4] = { i3a, i3b, i3a, i3b };
            #pragma unroll
            for (int kk = 0; kk < 4; kk++) {
                uint32_t a[4] = { ac2[mt][2 * kk][0], ac2[mt][2 * kk][1],
                                  ac2[mt][2 * kk + 1][0], ac2[mt][2 * kk + 1][1] };
                mma16816f(c, a, B3f[kk][0], B3f[kk][1]);
            }

            // residual bases via shuffle (lane r holds bases of row warpRow+r)
            float bxA = __shfl_sync(0xffffffffu, bx, mt * 16 + g);
            float byA = __shfl_sync(0xffffffffu, by, mt * 16 + g);
            float bzA = __shfl_sync(0xffffffffu, bz, mt * 16 + g);
            float bxB = __shfl_sync(0xffffffffu, bx, mt * 16 + g + 8);
            float byB = __shfl_sync(0xffffffffu, by, mt * 16 + g + 8);
            float bzB = __shfl_sync(0xffffffffu, bz, mt * 16 + g + 8);

            int rA = tile * 128 + warpRow + mt * 16 + g;
            int rB = rA + 8;
            if (tig == 0) {      // C cols 0,1 = out.x, out.y
                out[rA * 3 + 0] = bxA + c[0];
                out[rA * 3 + 1] = byA + c[1];
                out[rB * 3 + 0] = bxB + c[2];
                out[rB * 3 + 1] = byB + c[3];
            } else if (tig == 1) {  // C col 2 = out.z
                out[rA * 3 + 2] = bzA + c[0];
                out[rB * 3 + 2] = bzB + c[2];
            }
        }
        __syncwarp();   // all lanes done reading XS before next tile overwrites
    }
}

extern "C" void kernel_launch(void* const* d_in, const int* in_sizes, int n_in,
                              void* d_out, int out_size) {
    const float* bases   = (const float*)d_in[0];
    const float* normals = (const float*)d_in[1];
    const float* enc     = (const float*)d_in[2];
    const float* W1      = (const float*)d_in[3];
    const float* b1      = (const float*)d_in[4];
    const float* W2      = (const float*)d_in[5];
    const float* b2      = (const float*)d_in[6];
    const float* W3      = (const float*)d_in[7];
    const float* b3      = (const float*)d_in[8];
    float* out = (float*)d_out;

    cudaFuncSetAttribute(fused_encode_mlp,
                         cudaFuncAttributeMaxDynamicSharedMemorySize, SMEM_BYTES);

    // persistent: 148 SMs x 4 CTAs (smem-limited, 16 warps/SM)
    fused_encode_mlp<<<592, 128, SMEM_BYTES>>>(bases, normals, enc,
                                               W1, b1, W2, b2, W3, b3, out);
}